// round 10
// baseline (speedup 1.0000x reference)
#include <cuda_runtime.h>
#include <cuda_fp16.h>
#include <cstdint>
#include <math.h>

// ============================================================================
// MoE (top-2 of 8 experts), D=1024, H=4096, O=1024, T=8192 tokens.
// GEMMs: mma.sync fp16 m16n8k16 fp32-acc. 512 threads / 16 warps per CTA
// (4 warps/SMSP for latency hiding), warp tile 64x32, CTA tile 128x256,
// BK=64 halfs, 3-stage cp.async. GEMM1 at launch index 3 (ncu-captured).
// ============================================================================

#define T_TOK   8192
#define DMODEL  1024
#define DHID    4096
#define DOUTD   1024
#define NEXP    8
#define ROWS_CAP 17408
#define MAX_MTILES 136

#define BM 128
#define BN 256
#define BK 64                               // halfs per chunk = 128 B per row
#define NTHREADS 512

#define SMEM_A_BYTES (BM * BK * 2)          // 16384
#define SMEM_B_BYTES (BN * BK * 2)          // 32768
#define SMEM_STAGE   (SMEM_A_BYTES + SMEM_B_BYTES)
#define NSTAGE 3
#define DSMEM_BYTES  (NSTAGE * SMEM_STAGE)  // 147456

// ---------------- device scratch ----------------
__device__ __half g_perm[(size_t)ROWS_CAP * DMODEL];
__device__ __half g_h   [(size_t)ROWS_CAP * DHID];
__device__ float  g_y   [(size_t)ROWS_CAP * DOUTD];
__device__ __half g_w1h [(size_t)NEXP * DHID * DMODEL];
__device__ __half g_w2h [(size_t)NEXP * DOUTD * DHID];
__device__ float g_probs[T_TOK * NEXP];
__device__ float g_gate [T_TOK * 2];
__device__ int   g_topk [T_TOK * 2];
__device__ int   g_spos [T_TOK * 2];
__device__ int   g_counts[NEXP];
__device__ int   g_cursor[NEXP];
__device__ int   g_offsets[NEXP + 1];
__device__ float g_lb[1];
__device__ int   g_done;

// ---------------- PTX helpers ----------------
__device__ __forceinline__ uint32_t smem_to_u32(const void* p) {
    uint32_t a;
    asm("{ .reg .u64 t; cvta.to.shared.u64 t, %1; cvt.u32.u64 %0, t; }" : "=r"(a) : "l"(p));
    return a;
}
__device__ __forceinline__ uint32_t f2h2(float lo, float hi) {
    uint32_t r;
    asm("cvt.rn.f16x2.f32 %0, %1, %2;" : "=r"(r) : "f"(hi), "f"(lo));
    return r;
}
__device__ __forceinline__ uint32_t lds_u(uint32_t a) {
    uint32_t v;
    asm volatile("ld.shared.b32 %0, [%1];" : "=r"(v) : "r"(a));
    return v;
}
#define CP_ASYNC16(dst, src) \
    asm volatile("cp.async.cg.shared.global [%0], [%1], 16;" :: "r"(dst), "l"(src) : "memory")
#define CP_COMMIT() asm volatile("cp.async.commit_group;" ::: "memory")
#define CP_WAIT1()  asm volatile("cp.async.wait_group 1;" ::: "memory")
#define CP_WAIT0()  asm volatile("cp.async.wait_group 0;" ::: "memory")

__device__ __forceinline__ void mma16816(float* c, const uint32_t* a, uint32_t b0, uint32_t b1) {
    asm volatile(
        "mma.sync.aligned.m16n8k16.row.col.f32.f16.f16.f32 "
        "{%0,%1,%2,%3}, {%4,%5,%6,%7}, {%8,%9}, {%0,%1,%2,%3};"
        : "+f"(c[0]), "+f"(c[1]), "+f"(c[2]), "+f"(c[3])
        : "r"(a[0]), "r"(a[1]), "r"(a[2]), "r"(a[3]), "r"(b0), "r"(b1));
}

// ============================================================================
// Launch 0: fp32 -> fp16 conversion of both weight tensors + zero counts
// ============================================================================
__global__ void roundall_kernel(const float* __restrict__ w1, __half* __restrict__ w1h,
                                const float* __restrict__ w2, __half* __restrict__ w2h) {
    if (blockIdx.x == 0 && threadIdx.x < NEXP) g_counts[threadIdx.x] = 0;
    const int n4 = NEXP * DHID * DMODEL / 4;
    int stride = gridDim.x * blockDim.x;
    for (int i = blockIdx.x * blockDim.x + threadIdx.x; i < n4; i += stride) {
        float4 v = ((const float4*)w1)[i];
        ((uint2*)w1h)[i] = make_uint2(f2h2(v.x, v.y), f2h2(v.z, v.w));
        float4 u = ((const float4*)w2)[i];
        ((uint2*)w2h)[i] = make_uint2(f2h2(u.x, u.y), f2h2(u.z, u.w));
    }
}

// ============================================================================
// Launch 1: router + (last block) setup
// ============================================================================
__global__ void router_kernel(const float* __restrict__ x, const float* __restrict__ rw,
                              const float* __restrict__ rb) {
    int warp = threadIdx.x >> 5, lane = threadIdx.x & 31;
    int t = blockIdx.x * 8 + warp;
    const float* xp = x + (size_t)t * DMODEL;
    float xr[32];
#pragma unroll
    for (int i = 0; i < 32; i++) xr[i] = xp[i * 32 + lane];
    float lg[NEXP];
#pragma unroll
    for (int e = 0; e < NEXP; e++) {
        const float* wp = rw + e * DMODEL;
        float s = 0.f;
#pragma unroll
        for (int i = 0; i < 32; i++) s += xr[i] * wp[i * 32 + lane];
#pragma unroll
        for (int o = 16; o; o >>= 1) s += __shfl_xor_sync(0xFFFFFFFFu, s, o);
        lg[e] = s + rb[e];
    }
    if (lane == 0) {
        float mx = lg[0];
#pragma unroll
        for (int e = 1; e < NEXP; e++) mx = fmaxf(mx, lg[e]);
        float p[NEXP], sum = 0.f;
#pragma unroll
        for (int e = 0; e < NEXP; e++) { p[e] = expf(lg[e] - mx); sum += p[e]; }
        float inv = 1.f / sum;
#pragma unroll
        for (int e = 0; e < NEXP; e++) { p[e] *= inv; g_probs[t * NEXP + e] = p[e]; }
        int i0 = 0;
#pragma unroll
        for (int e = 1; e < NEXP; e++) if (p[e] > p[i0]) i0 = e;
        int i1 = (i0 == 0) ? 1 : 0;
#pragma unroll
        for (int e = 0; e < NEXP; e++) if (e != i0 && e != i1 && p[e] > p[i1]) i1 = e;
        float w0 = p[i0], w1 = p[i1], ws = 1.f / (w0 + w1);
        g_gate[t * 2 + 0] = w0 * ws;
        g_gate[t * 2 + 1] = w1 * ws;
        g_topk[t * 2 + 0] = i0;
        g_topk[t * 2 + 1] = i1;
        atomicAdd(&g_counts[i0], 1);
        atomicAdd(&g_counts[i1], 1);
        __threadfence();
    }
    __syncthreads();
    __shared__ int s_last;
    if (threadIdx.x == 0) {
        int old = atomicAdd(&g_done, 1);
        s_last = (old == gridDim.x - 1);
    }
    __syncthreads();
    if (!s_last) return;

    __shared__ float sp[NEXP];
    if (warp < NEXP) {
        float s = 0.f;
        for (int tt = lane; tt < T_TOK; tt += 32) s += __ldcg(&g_probs[tt * NEXP + warp]);
#pragma unroll
        for (int o = 16; o; o >>= 1) s += __shfl_xor_sync(0xFFFFFFFFu, s, o);
        if (lane == 0) sp[warp] = s;
    }
    __syncthreads();
    if (threadIdx.x == 0) {
        int off = 0;
        float l = 0.f;
        for (int e = 0; e < NEXP; e++) {
            int c = __ldcg(&g_counts[e]);
            g_offsets[e] = off;
            off += ((c + BM - 1) / BM) * BM;
            g_cursor[e] = 0;
            l += ((float)c / (float)(T_TOK * 2)) * (sp[e] / (float)T_TOK);
        }
        g_offsets[NEXP] = off;
        g_lb[0] = 0.01f * (float)NEXP * l;
        g_done = 0;
    }
}

// ============================================================================
// Launch 2: gather; converts x rows to fp16 in grouped layout
// ============================================================================
__global__ void scatter_kernel(const float* __restrict__ x) {
    int wslot = blockIdx.x * 8 + (threadIdx.x >> 5);
    int lane = threadIdx.x & 31;
    int t = wslot >> 1, k = wslot & 1;
    int e = g_topk[t * 2 + k];
    int pos = 0;
    if (lane == 0) {
        pos = g_offsets[e] + atomicAdd(&g_cursor[e], 1);
        g_spos[t * 2 + k] = pos;
    }
    pos = __shfl_sync(0xFFFFFFFFu, pos, 0);
    const float4* src = (const float4*)(x + (size_t)t * DMODEL);
    uint2* dst = (uint2*)(g_perm + (size_t)pos * DMODEL);
#pragma unroll
    for (int j = 0; j < 8; j++) {
        float4 v = src[lane + j * 32];
        dst[lane + j * 32] = make_uint2(f2h2(v.x, v.y), f2h2(v.z, v.w));
    }
}

// ============================================================================
// Launches 3,4: grouped fp16 GEMM. CTA tile 128x256, BK=64, 16 warps
// (2Mx8N, warp tile 64x32), 3-stage cp.async, single-buffer fragments
// (4 warps/SMSP cover the LDS latency).
// MODE 0: A=g_perm -> C=g_h (relu, fp16). MODE 1: A=g_h -> C=g_y (f32).
// ============================================================================
template <int KTOT, int NTOT, bool RELU, int MODE>
__global__ __launch_bounds__(NTHREADS, 1) void gemm_kernel(const __half* __restrict__ Bw,
                                                           const float* __restrict__ bias) {
    const __half* A = (MODE == 0) ? g_perm : g_h;

    int row0 = (int)blockIdx.y * BM;
    if (row0 >= g_offsets[NEXP]) return;
    int e = 0;
#pragma unroll
    for (int i = 1; i < NEXP; i++) if (row0 >= g_offsets[i]) e = i;
    int n0 = blockIdx.x * BN;

    extern __shared__ char smem[];
    uint32_t sb = smem_to_u32(smem);
    int tid = threadIdx.x;
    int wid = tid >> 5, lane = tid & 31;
    int g = lane >> 2, t = lane & 3;
    int wm = wid >> 3;          // 0..1 -> m offset wm*64
    int wn = wid & 7;           // 0..7 -> n offset wn*32

    const __half* Ag = A + (size_t)row0 * KTOT;
    const __half* Bg = Bw + (size_t)e * NTOT * KTOT + (size_t)n0 * KTOT;

    auto load_chunk = [&](int it, int buf) {
        int k0 = it * BK;
        uint32_t sA = sb + buf * SMEM_STAGE;
        uint32_t sB = sA + SMEM_A_BYTES;
#pragma unroll
        for (int i = 0; i < 2; i++) {           // A: 128 rows x 8 x 16B = 1024
            int idx = tid + i * NTHREADS;
            int r = idx >> 3, c8 = idx & 7;
            uint32_t dst = sA + (uint32_t)(r * 8 + (c8 ^ (r & 7))) * 16;
            CP_ASYNC16(dst, Ag + (size_t)r * KTOT + k0 + c8 * 8);
        }
#pragma unroll
        for (int i = 0; i < 4; i++) {           // B: 256 rows x 8 x 16B = 2048
            int idx = tid + i * NTHREADS;
            int r = idx >> 3, c8 = idx & 7;
            uint32_t dst = sB + (uint32_t)(r * 8 + (c8 ^ (r & 7))) * 16;
            CP_ASYNC16(dst, Bg + (size_t)r * KTOT + k0 + c8 * 8);
        }
        CP_COMMIT();
    };

    float acc[4][4][4];
#pragma unroll
    for (int mt = 0; mt < 4; mt++)
#pragma unroll
        for (int nt = 0; nt < 4; nt++)
#pragma unroll
            for (int j = 0; j < 4; j++) acc[mt][nt][j] = 0.f;

    constexpr int NIT = KTOT / BK;
    load_chunk(0, 0);
    load_chunk(1, 1);

    int buf = 0;
    for (int it = 0; it < NIT; ++it) {
        if (it == NIT - 1) { CP_WAIT0(); } else { CP_WAIT1(); }
        __syncthreads();
        if (it + 2 < NIT) {
            int nb = buf + 2; if (nb >= NSTAGE) nb -= NSTAGE;
            load_chunk(it + 2, nb);
        }

        uint32_t sA = sb + buf * SMEM_STAGE;
        uint32_t sB = sA + SMEM_A_BYTES;

#pragma unroll
        for (int kk = 0; kk < 4; kk++) {        // k-slab of 16 halfs
            uint32_t col0 = (uint32_t)(((2 * kk) ^ g) * 16 + t * 4);
            uint32_t col1 = (uint32_t)(((2 * kk + 1) ^ g) * 16 + t * 4);
            uint32_t af[4][4];
#pragma unroll
            for (int mt = 0; mt < 4; mt++) {
                uint32_t r0 = (uint32_t)(wm * 64 + mt * 16 + g) * 128;
                af[mt][0] = lds_u(sA + r0 + col0);
                af[mt][1] = lds_u(sA + r0 + 8 * 128 + col0);
                af[mt][2] = lds_u(sA + r0 + col1);
                af[mt][3] = lds_u(sA + r0 + 8 * 128 + col1);
            }
#pragma unroll
            for (int nt = 0; nt < 4; nt++) {
                uint32_t rn = (uint32_t)(wn * 32 + nt * 8 + g) * 128;
                uint32_t b0 = lds_u(sB + rn + col0);
                uint32_t b1 = lds_u(sB + rn + col1);
#pragma unroll
                for (int mt = 0; mt < 4; mt++)
                    mma16816(acc[mt][nt], af[mt], b0, b1);
            }
        }
        buf = (buf == NSTAGE - 1) ? 0 : buf + 1;
    }

    // ---- epilogue: bias (+relu); MODE0 -> fp16 g_h, MODE1 -> f32 g_y ----
    const float* bp = bias + (size_t)e * NTOT + n0 + wn * 32;
#pragma unroll
    for (int nt = 0; nt < 4; nt++) {
        int col = nt * 8 + 2 * t;
        float2 bv = *(const float2*)(bp + col);
#pragma unroll
        for (int mt = 0; mt < 4; mt++) {
            int r0 = row0 + wm * 64 + mt * 16 + g;
            float v[4];
            v[0] = acc[mt][nt][0] + bv.x; v[1] = acc[mt][nt][1] + bv.y;
            v[2] = acc[mt][nt][2] + bv.x; v[3] = acc[mt][nt][3] + bv.y;
            if (RELU) {
#pragma unroll
                for (int j = 0; j < 4; j++) v[j] = fmaxf(v[j], 0.f);
            }
            if (MODE == 0) {
                uint32_t* cp0 = (uint32_t*)(g_h + (size_t)r0 * NTOT + n0 + wn * 32 + col);
                cp0[0] = f2h2(v[0], v[1]);
                *(uint32_t*)((__half*)cp0 + (size_t)8 * NTOT) = f2h2(v[2], v[3]);
            } else {
                float* cp0 = g_y + (size_t)r0 * NTOT + n0 + wn * 32 + col;
                *(float2*)cp0 = make_float2(v[0], v[1]);
                *(float2*)(cp0 + (size_t)8 * NTOT) = make_float2(v[2], v[3]);
            }
        }
    }
}

// ============================================================================
// Launch 5: combine.  Launch 6: lb tail.
// ============================================================================
__global__ void combine_kernel(float* __restrict__ out) {
    int t = blockIdx.x;
    int d4 = threadIdx.x;
    float w0 = g_gate[t * 2 + 0], w1 = g_gate[t * 2 + 1];
    int p0 = g_spos[t * 2 + 0], p1 = g_spos[t * 2 + 1];
    float4 y0 = ((const float4*)(g_y + (size_t)p0 * DOUTD))[d4];
    float4 y1 = ((const float4*)(g_y + (size_t)p1 * DOUTD))[d4];
    float4 o;
    o.x = w0 * y0.x + w1 * y1.x;
    o.y = w0 * y0.y + w1 * y1.y;
    o.z = w0 * y0.z + w1 * y1.z;
    o.w = w0 * y0.w + w1 * y1.w;
    ((float4*)(out + (size_t)t * DOUTD))[d4] = o;
}

__global__ void lb_write_kernel(float* dst, int n) {
    int i = threadIdx.x;
    if (i < n) dst[i] = g_lb[0];
}

// ============================================================================
extern "C" void kernel_launch(void* const* d_in, const int* in_sizes, int n_in,
                              void* d_out, int out_size) {
    const float* x  = (const float*)d_in[0];
    const float* rw = (const float*)d_in[1];
    const float* rb = (const float*)d_in[2];
    const float* w1 = (const float*)d_in[3];
    const float* b1 = (const float*)d_in[4];
    const float* w2 = (const float*)d_in[5];
    const float* b2 = (const float*)d_in[6];
    float* out = (float*)d_out;

    cudaFuncSetAttribute(gemm_kernel<DMODEL, DHID, true, 0>,
                         cudaFuncAttributeMaxDynamicSharedMemorySize, DSMEM_BYTES);
    cudaFuncSetAttribute(gemm_kernel<DHID, DOUTD, false, 1>,
                         cudaFuncAttributeMaxDynamicSharedMemorySize, DSMEM_BYTES);

    __half* w1h; cudaGetSymbolAddress((void**)&w1h, g_w1h);
    __half* w2h; cudaGetSymbolAddress((void**)&w2h, g_w2h);

    // launch 0: weight fp16 prepass (+zero counts)
    roundall_kernel<<<2048, 256>>>(w1, w1h, w2, w2h);
    // launch 1: router + fused setup
    router_kernel<<<T_TOK / 8, 256>>>(x, rw, rb);
    // launch 2: gather (fp16)
    scatter_kernel<<<(T_TOK * 2) / 8, 256>>>(x);
    // launch 3 (ncu-captured): GEMM1
    gemm_kernel<DMODEL, DHID, true, 0>
        <<<dim3(DHID / BN, MAX_MTILES, 1), NTHREADS, DSMEM_BYTES>>>(w1h, b1);
    // launch 4: GEMM2
    gemm_kernel<DHID, DOUTD, false, 1>
        <<<dim3(DOUTD / BN, MAX_MTILES, 1), NTHREADS, DSMEM_BYTES>>>(w2h, b2);
    // launch 5: combine
    combine_kernel<<<T_TOK, 256>>>(out);

    long long tail = (long long)out_size - (long long)T_TOK * DOUTD;
    if (tail > 0) {
        int n = (tail > 32) ? 32 : (int)tail;
        lb_write_kernel<<<1, 32>>>(out + (size_t)T_TOK * DOUTD, n);
    }
}

// round 11
// speedup vs baseline: 1.0384x; 1.0384x over previous
#include <cuda_runtime.h>
#include <cuda_fp16.h>
#include <cstdint>
#include <math.h>

// ============================================================================
// MoE (top-2 of 8 experts), D=1024, H=4096, O=1024, T=8192 tokens.
// GEMMs: mma.sync fp16 m16n8k16 fp32-acc (legacy tensor pipe is at its
// HMMA instruction-rate ceiling ~61% pipe-active; R9 config restored).
// This round: hide the w2 fp16-conversion prepass under GEMM1 via a
// stream-fork (graph-capturable event fork/join); fuse lb tail into combine.
// ============================================================================

#define T_TOK   8192
#define DMODEL  1024
#define DHID    4096
#define DOUTD   1024
#define NEXP    8
#define ROWS_CAP 17408
#define MAX_MTILES 136

#define BM 128
#define BN 256
#define BK 64                               // halfs per chunk = 128 B per row

#define SMEM_A_BYTES (BM * BK * 2)          // 16384
#define SMEM_B_BYTES (BN * BK * 2)          // 32768
#define SMEM_STAGE   (SMEM_A_BYTES + SMEM_B_BYTES)
#define NSTAGE 3
#define DSMEM_BYTES  (NSTAGE * SMEM_STAGE)  // 147456

// ---------------- device scratch ----------------
__device__ __half g_perm[(size_t)ROWS_CAP * DMODEL];
__device__ __half g_h   [(size_t)ROWS_CAP * DHID];
__device__ float  g_y   [(size_t)ROWS_CAP * DOUTD];
__device__ __half g_w1h [(size_t)NEXP * DHID * DMODEL];
__device__ __half g_w2h [(size_t)NEXP * DOUTD * DHID];
__device__ float g_probs[T_TOK * NEXP];
__device__ float g_gate [T_TOK * 2];
__device__ int   g_topk [T_TOK * 2];
__device__ int   g_spos [T_TOK * 2];
__device__ int   g_counts[NEXP];
__device__ int   g_cursor[NEXP];
__device__ int   g_offsets[NEXP + 1];
__device__ float g_lb[1];
__device__ int   g_done;

// ---------------- PTX helpers ----------------
__device__ __forceinline__ uint32_t smem_to_u32(const void* p) {
    uint32_t a;
    asm("{ .reg .u64 t; cvta.to.shared.u64 t, %1; cvt.u32.u64 %0, t; }" : "=r"(a) : "l"(p));
    return a;
}
__device__ __forceinline__ uint32_t f2h2(float lo, float hi) {
    uint32_t r;
    asm("cvt.rn.f16x2.f32 %0, %1, %2;" : "=r"(r) : "f"(hi), "f"(lo));
    return r;
}
__device__ __forceinline__ uint32_t lds_u(uint32_t a) {
    uint32_t v;
    asm volatile("ld.shared.b32 %0, [%1];" : "=r"(v) : "r"(a));
    return v;
}
#define CP_ASYNC16(dst, src) \
    asm volatile("cp.async.cg.shared.global [%0], [%1], 16;" :: "r"(dst), "l"(src) : "memory")
#define CP_COMMIT() asm volatile("cp.async.commit_group;" ::: "memory")
#define CP_WAIT1()  asm volatile("cp.async.wait_group 1;" ::: "memory")
#define CP_WAIT0()  asm volatile("cp.async.wait_group 0;" ::: "memory")

__device__ __forceinline__ void mma16816(float* c, const uint32_t* a, uint32_t b0, uint32_t b1) {
    asm volatile(
        "mma.sync.aligned.m16n8k16.row.col.f32.f16.f16.f32 "
        "{%0,%1,%2,%3}, {%4,%5,%6,%7}, {%8,%9}, {%0,%1,%2,%3};"
        : "+f"(c[0]), "+f"(c[1]), "+f"(c[2]), "+f"(c[3])
        : "r"(a[0]), "r"(a[1]), "r"(a[2]), "r"(a[3]), "r"(b0), "r"(b1));
}

// ============================================================================
// fp32 -> fp16 weight conversion kernels (w1 also zeroes expert counts)
// ============================================================================
__global__ void w1conv_kernel(const float* __restrict__ w1, __half* __restrict__ w1h) {
    if (blockIdx.x == 0 && threadIdx.x < NEXP) g_counts[threadIdx.x] = 0;
    const int n4 = NEXP * DHID * DMODEL / 4;
    int stride = gridDim.x * blockDim.x;
    for (int i = blockIdx.x * blockDim.x + threadIdx.x; i < n4; i += stride) {
        float4 v = ((const float4*)w1)[i];
        ((uint2*)w1h)[i] = make_uint2(f2h2(v.x, v.y), f2h2(v.z, v.w));
    }
}
__global__ void w2conv_kernel(const float* __restrict__ w2, __half* __restrict__ w2h) {
    const int n4 = NEXP * DOUTD * DHID / 4;
    int stride = gridDim.x * blockDim.x;
    for (int i = blockIdx.x * blockDim.x + threadIdx.x; i < n4; i += stride) {
        float4 u = ((const float4*)w2)[i];
        ((uint2*)w2h)[i] = make_uint2(f2h2(u.x, u.y), f2h2(u.z, u.w));
    }
}

// ============================================================================
// router + (last block) setup
// ============================================================================
__global__ void router_kernel(const float* __restrict__ x, const float* __restrict__ rw,
                              const float* __restrict__ rb) {
    int warp = threadIdx.x >> 5, lane = threadIdx.x & 31;
    int t = blockIdx.x * 8 + warp;
    const float* xp = x + (size_t)t * DMODEL;
    float xr[32];
#pragma unroll
    for (int i = 0; i < 32; i++) xr[i] = xp[i * 32 + lane];
    float lg[NEXP];
#pragma unroll
    for (int e = 0; e < NEXP; e++) {
        const float* wp = rw + e * DMODEL;
        float s = 0.f;
#pragma unroll
        for (int i = 0; i < 32; i++) s += xr[i] * wp[i * 32 + lane];
#pragma unroll
        for (int o = 16; o; o >>= 1) s += __shfl_xor_sync(0xFFFFFFFFu, s, o);
        lg[e] = s + rb[e];
    }
    if (lane == 0) {
        float mx = lg[0];
#pragma unroll
        for (int e = 1; e < NEXP; e++) mx = fmaxf(mx, lg[e]);
        float p[NEXP], sum = 0.f;
#pragma unroll
        for (int e = 0; e < NEXP; e++) { p[e] = expf(lg[e] - mx); sum += p[e]; }
        float inv = 1.f / sum;
#pragma unroll
        for (int e = 0; e < NEXP; e++) { p[e] *= inv; g_probs[t * NEXP + e] = p[e]; }
        int i0 = 0;
#pragma unroll
        for (int e = 1; e < NEXP; e++) if (p[e] > p[i0]) i0 = e;
        int i1 = (i0 == 0) ? 1 : 0;
#pragma unroll
        for (int e = 0; e < NEXP; e++) if (e != i0 && e != i1 && p[e] > p[i1]) i1 = e;
        float w0 = p[i0], w1 = p[i1], ws = 1.f / (w0 + w1);
        g_gate[t * 2 + 0] = w0 * ws;
        g_gate[t * 2 + 1] = w1 * ws;
        g_topk[t * 2 + 0] = i0;
        g_topk[t * 2 + 1] = i1;
        atomicAdd(&g_counts[i0], 1);
        atomicAdd(&g_counts[i1], 1);
        __threadfence();
    }
    __syncthreads();
    __shared__ int s_last;
    if (threadIdx.x == 0) {
        int old = atomicAdd(&g_done, 1);
        s_last = (old == gridDim.x - 1);
    }
    __syncthreads();
    if (!s_last) return;

    __shared__ float sp[NEXP];
    if (warp < NEXP) {
        float s = 0.f;
        for (int tt = lane; tt < T_TOK; tt += 32) s += __ldcg(&g_probs[tt * NEXP + warp]);
#pragma unroll
        for (int o = 16; o; o >>= 1) s += __shfl_xor_sync(0xFFFFFFFFu, s, o);
        if (lane == 0) sp[warp] = s;
    }
    __syncthreads();
    if (threadIdx.x == 0) {
        int off = 0;
        float l = 0.f;
        for (int e = 0; e < NEXP; e++) {
            int c = __ldcg(&g_counts[e]);
            g_offsets[e] = off;
            off += ((c + BM - 1) / BM) * BM;
            g_cursor[e] = 0;
            l += ((float)c / (float)(T_TOK * 2)) * (sp[e] / (float)T_TOK);
        }
        g_offsets[NEXP] = off;
        g_lb[0] = 0.01f * (float)NEXP * l;
        g_done = 0;
    }
}

// ============================================================================
// gather: converts x rows to fp16 in grouped layout
// ============================================================================
__global__ void scatter_kernel(const float* __restrict__ x) {
    int wslot = blockIdx.x * 8 + (threadIdx.x >> 5);
    int lane = threadIdx.x & 31;
    int t = wslot >> 1, k = wslot & 1;
    int e = g_topk[t * 2 + k];
    int pos = 0;
    if (lane == 0) {
        pos = g_offsets[e] + atomicAdd(&g_cursor[e], 1);
        g_spos[t * 2 + k] = pos;
    }
    pos = __shfl_sync(0xFFFFFFFFu, pos, 0);
    const float4* src = (const float4*)(x + (size_t)t * DMODEL);
    uint2* dst = (uint2*)(g_perm + (size_t)pos * DMODEL);
#pragma unroll
    for (int j = 0; j < 8; j++) {
        float4 v = src[lane + j * 32];
        dst[lane + j * 32] = make_uint2(f2h2(v.x, v.y), f2h2(v.z, v.w));
    }
}

// ============================================================================
// Grouped fp16 GEMM (R9 config): CTA tile 128x256, BK=64, 8 warps (2Mx4N,
// warp tile 64x64), 3-stage cp.async, per-chunk fragment double-buffer.
// MODE 0: A=g_perm -> C=g_h (relu, fp16). MODE 1: A=g_h -> C=g_y (f32).
// ============================================================================
template <int KTOT, int NTOT, bool RELU, int MODE>
__global__ __launch_bounds__(256, 1) void gemm_kernel(const __half* __restrict__ Bw,
                                                      const float* __restrict__ bias) {
    const __half* A = (MODE == 0) ? g_perm : g_h;

    int row0 = (int)blockIdx.y * BM;
    if (row0 >= g_offsets[NEXP]) return;
    int e = 0;
#pragma unroll
    for (int i = 1; i < NEXP; i++) if (row0 >= g_offsets[i]) e = i;
    int n0 = blockIdx.x * BN;

    extern __shared__ char smem[];
    uint32_t sb = smem_to_u32(smem);
    int tid = threadIdx.x;
    int wid = tid >> 5, lane = tid & 31;
    int g = lane >> 2, t = lane & 3;
    int wm = wid >> 2;
    int wn = wid & 3;

    const __half* Ag = A + (size_t)row0 * KTOT;
    const __half* Bg = Bw + (size_t)e * NTOT * KTOT + (size_t)n0 * KTOT;

    auto load_chunk = [&](int it, int buf) {
        int k0 = it * BK;
        uint32_t sA = sb + buf * SMEM_STAGE;
        uint32_t sB = sA + SMEM_A_BYTES;
#pragma unroll
        for (int i = 0; i < 4; i++) {           // A: 128 rows x 8 x 16B
            int idx = tid + i * 256;
            int r = idx >> 3, c8 = idx & 7;
            uint32_t dst = sA + (uint32_t)(r * 8 + (c8 ^ (r & 7))) * 16;
            CP_ASYNC16(dst, Ag + (size_t)r * KTOT + k0 + c8 * 8);
        }
#pragma unroll
        for (int i = 0; i < 8; i++) {           // B: 256 rows x 8 x 16B
            int idx = tid + i * 256;
            int r = idx >> 3, c8 = idx & 7;
            uint32_t dst = sB + (uint32_t)(r * 8 + (c8 ^ (r & 7))) * 16;
            CP_ASYNC16(dst, Bg + (size_t)r * KTOT + k0 + c8 * 8);
        }
        CP_COMMIT();
    };

    float acc[4][8][4];
#pragma unroll
    for (int mt = 0; mt < 4; mt++)
#pragma unroll
        for (int nt = 0; nt < 8; nt++)
#pragma unroll
            for (int j = 0; j < 4; j++) acc[mt][nt][j] = 0.f;

    constexpr int NIT = KTOT / BK;
    load_chunk(0, 0);
    load_chunk(1, 1);

    int buf = 0;
    for (int it = 0; it < NIT; ++it) {
        if (it == NIT - 1) { CP_WAIT0(); } else { CP_WAIT1(); }
        __syncthreads();
        if (it + 2 < NIT) {
            int nb = buf + 2; if (nb >= NSTAGE) nb -= NSTAGE;
            load_chunk(it + 2, nb);
        }

        uint32_t sA = sb + buf * SMEM_STAGE;
        uint32_t sB = sA + SMEM_A_BYTES;

        auto lfrag = [&](int kk, uint32_t* a_f, uint32_t* b_f) {
            uint32_t col0 = (uint32_t)(((2 * kk) ^ g) * 16 + t * 4);
            uint32_t col1 = (uint32_t)(((2 * kk + 1) ^ g) * 16 + t * 4);
#pragma unroll
            for (int mt = 0; mt < 4; mt++) {
                uint32_t r0 = (uint32_t)(wm * 64 + mt * 16 + g) * 128;
                a_f[mt * 4 + 0] = lds_u(sA + r0 + col0);
                a_f[mt * 4 + 1] = lds_u(sA + r0 + 8 * 128 + col0);
                a_f[mt * 4 + 2] = lds_u(sA + r0 + col1);
                a_f[mt * 4 + 3] = lds_u(sA + r0 + 8 * 128 + col1);
            }
#pragma unroll
            for (int nt = 0; nt < 8; nt++) {
                uint32_t rn = (uint32_t)(wn * 64 + nt * 8 + g) * 128;
                b_f[nt * 2 + 0] = lds_u(sB + rn + col0);
                b_f[nt * 2 + 1] = lds_u(sB + rn + col1);
            }
        };

        uint32_t afr[2][16], bfr[2][16];
        lfrag(0, afr[0], bfr[0]);
#pragma unroll
        for (int kk = 0; kk < 4; kk++) {
            int cur = kk & 1;
            if (kk < 3) lfrag(kk + 1, afr[cur ^ 1], bfr[cur ^ 1]);
#pragma unroll
            for (int nt = 0; nt < 8; nt++)
#pragma unroll
                for (int mt = 0; mt < 4; mt++)
                    mma16816(acc[mt][nt], &afr[cur][mt * 4],
                             bfr[cur][nt * 2], bfr[cur][nt * 2 + 1]);
        }
        buf = (buf == NSTAGE - 1) ? 0 : buf + 1;
    }

    // ---- epilogue ----
    const float* bp = bias + (size_t)e * NTOT + n0 + wn * 64;
#pragma unroll
    for (int nt = 0; nt < 8; nt++) {
        int col = nt * 8 + 2 * t;
        float2 bv = *(const float2*)(bp + col);
#pragma unroll
        for (int mt = 0; mt < 4; mt++) {
            int r0 = row0 + wm * 64 + mt * 16 + g;
            float v[4];
            v[0] = acc[mt][nt][0] + bv.x; v[1] = acc[mt][nt][1] + bv.y;
            v[2] = acc[mt][nt][2] + bv.x; v[3] = acc[mt][nt][3] + bv.y;
            if (RELU) {
#pragma unroll
                for (int j = 0; j < 4; j++) v[j] = fmaxf(v[j], 0.f);
            }
            if (MODE == 0) {
                uint32_t* cp0 = (uint32_t*)(g_h + (size_t)r0 * NTOT + n0 + wn * 64 + col);
                cp0[0] = f2h2(v[0], v[1]);
                *(uint32_t*)((__half*)cp0 + (size_t)8 * NTOT) = f2h2(v[2], v[3]);
            } else {
                float* cp0 = g_y + (size_t)r0 * NTOT + n0 + wn * 64 + col;
                *(float2*)cp0 = make_float2(v[0], v[1]);
                *(float2*)(cp0 + (size_t)8 * NTOT) = make_float2(v[2], v[3]);
            }
        }
    }
}

// ============================================================================
// combine (+ lb tail written by the extra trailing block)
// ============================================================================
__global__ void combine_kernel(float* __restrict__ out, int out_size) {
    int t = blockIdx.x;
    if (t >= T_TOK) {   // trailing block: lb_loss tail
        long long tail = (long long)out_size - (long long)T_TOK * DOUTD;
        if (threadIdx.x < tail && threadIdx.x < 256)
            out[(size_t)T_TOK * DOUTD + threadIdx.x] = g_lb[0];
        return;
    }
    int d4 = threadIdx.x;
    float w0 = g_gate[t * 2 + 0], w1 = g_gate[t * 2 + 1];
    int p0 = g_spos[t * 2 + 0], p1 = g_spos[t * 2 + 1];
    float4 y0 = ((const float4*)(g_y + (size_t)p0 * DOUTD))[d4];
    float4 y1 = ((const float4*)(g_y + (size_t)p1 * DOUTD))[d4];
    float4 o;
    o.x = w0 * y0.x + w1 * y1.x;
    o.y = w0 * y0.y + w1 * y1.y;
    o.z = w0 * y0.z + w1 * y1.z;
    o.w = w0 * y0.w + w1 * y1.w;
    ((float4*)(out + (size_t)t * DOUTD))[d4] = o;
}

// ============================================================================
extern "C" void kernel_launch(void* const* d_in, const int* in_sizes, int n_in,
                              void* d_out, int out_size) {
    const float* x  = (const float*)d_in[0];
    const float* rw = (const float*)d_in[1];
    const float* rb = (const float*)d_in[2];
    const float* w1 = (const float*)d_in[3];
    const float* b1 = (const float*)d_in[4];
    const float* w2 = (const float*)d_in[5];
    const float* b2 = (const float*)d_in[6];
    float* out = (float*)d_out;

    cudaFuncSetAttribute(gemm_kernel<DMODEL, DHID, true, 0>,
                         cudaFuncAttributeMaxDynamicSharedMemorySize, DSMEM_BYTES);
    cudaFuncSetAttribute(gemm_kernel<DHID, DOUTD, false, 1>,
                         cudaFuncAttributeMaxDynamicSharedMemorySize, DSMEM_BYTES);

    __half* w1h; cudaGetSymbolAddress((void**)&w1h, g_w1h);
    __half* w2h; cudaGetSymbolAddress((void**)&w2h, g_w2h);

    // Side stream + events for overlapping w2 conversion with the front of the
    // pipeline and GEMM1. Host-side objects only (no device allocation); the
    // fork/join event pattern is graph-capturable.
    cudaStream_t s1;
    cudaStreamCreateWithFlags(&s1, cudaStreamNonBlocking);
    cudaEvent_t evFork, evW2;
    cudaEventCreateWithFlags(&evFork, cudaEventDisableTiming);
    cudaEventCreateWithFlags(&evW2, cudaEventDisableTiming);

    cudaEventRecord(evFork, 0);            // fork point at start of main stream

    // main stream: launches 0..3 (gemm1 stays at capture index 3)
    w1conv_kernel<<<1024, 256>>>(w1, w1h);
    router_kernel<<<T_TOK / 8, 256>>>(x, rw, rb);
    scatter_kernel<<<(T_TOK * 2) / 8, 256>>>(x);
    gemm_kernel<DMODEL, DHID, true, 0>
        <<<dim3(DHID / BN, MAX_MTILES, 1), 256, DSMEM_BYTES>>>(w1h, b1);

    // side stream: w2 conversion, overlapped with everything above
    cudaStreamWaitEvent(s1, evFork, 0);
    w2conv_kernel<<<1024, 256, 0, s1>>>(w2, w2h);
    cudaEventRecord(evW2, s1);

    // join, then GEMM2 + combine(+lb tail)
    cudaStreamWaitEvent(0, evW2, 0);
    gemm_kernel<DHID, DOUTD, false, 1>
        <<<dim3(DOUTD / BN, MAX_MTILES, 1), 256, DSMEM_BYTES>>>(w2h, b2);
    combine_kernel<<<T_TOK + 1, 256>>>(out, out_size);

    cudaEventDestroy(evFork);
    cudaEventDestroy(evW2);
    cudaStreamDestroy(s1);
}